// round 4
// baseline (speedup 1.0000x reference)
#include <cuda_runtime.h>
#include <cuda_bf16.h>

// Problem constants (B=2, L=2048, C=1024, H=16, D=64)
#define BB 2
#define LL 2048
#define CC 1024
#define HH 16
#define DD 64
#define MTOT (BB * LL)   // 4096

// Scratch (device globals — no allocation allowed)
__device__ float g_q[MTOT * CC];
__device__ float g_k[MTOT * CC];
__device__ float g_v[MTOT * CC];
__device__ float g_y[MTOT * CC];

// ---------------------------------------------------------------------------
// GEMM + bias: Out[M,N] = A[M,K] @ W[K,N] + bias[N]
// M=4096, N=1024, K=1024 (all fixed, all divisible by tile sizes)
// Tiles: BM=128, BN=64, BK=16; 256 threads; 8x4 per-thread micro-tile.
// ---------------------------------------------------------------------------
__global__ __launch_bounds__(256) void gemm_bias_kernel(
    const float* __restrict__ A, const float* __restrict__ W,
    const float* __restrict__ bias, float* __restrict__ Out)
{
    const int M = MTOT, N = CC, K = CC;
    __shared__ float As[16][128];  // [k][m] layout for coalesced compute reads
    __shared__ float Bs[16][64];   // [k][n]

    const int tid = threadIdx.x;
    const int tx = tid & 15;       // 0..15 -> col group (4 cols each)
    const int ty = tid >> 4;       // 0..15 -> row group (8 rows each)
    const int m0 = blockIdx.y * 128;
    const int n0 = blockIdx.x * 64;

    float acc[8][4];
#pragma unroll
    for (int i = 0; i < 8; i++)
#pragma unroll
        for (int j = 0; j < 4; j++) acc[i][j] = 0.0f;

    for (int k0 = 0; k0 < K; k0 += 16) {
        // Load A tile: 128x16 = 2048 elems, 8 per thread (coalesced 16-wide rows)
#pragma unroll
        for (int i = 0; i < 8; i++) {
            int idx = tid + i * 256;
            int r = idx >> 4, c = idx & 15;
            As[c][r] = A[(size_t)(m0 + r) * K + k0 + c];
        }
        // Load W tile: 16x64 = 1024 elems, 4 per thread (coalesced 64-wide rows)
#pragma unroll
        for (int i = 0; i < 4; i++) {
            int idx = tid + i * 256;
            int r = idx >> 6, c = idx & 63;
            Bs[r][c] = W[(size_t)(k0 + r) * N + n0 + c];
        }
        __syncthreads();

#pragma unroll
        for (int kk = 0; kk < 16; kk++) {
            float a[8], b[4];
#pragma unroll
            for (int i = 0; i < 8; i++) a[i] = As[kk][ty * 8 + i];
#pragma unroll
            for (int j = 0; j < 4; j++) b[j] = Bs[kk][tx * 4 + j];
#pragma unroll
            for (int i = 0; i < 8; i++)
#pragma unroll
                for (int j = 0; j < 4; j++)
                    acc[i][j] = fmaf(a[i], b[j], acc[i][j]);
        }
        __syncthreads();
    }

#pragma unroll
    for (int i = 0; i < 8; i++) {
        int r = m0 + ty * 8 + i;
#pragma unroll
        for (int j = 0; j < 4; j++) {
            int cn = n0 + tx * 4 + j;
            Out[(size_t)r * N + cn] = acc[i][j] + bias[cn];
        }
    }
}

// ---------------------------------------------------------------------------
// Flash-style attention. Layout of Q/K/V/Y: (B, L, H*D) contiguous.
// One thread = one query row. Block = 64 threads (64 query rows).
// Grid: (L/64, B*H). K/V staged in 64x64 shared tiles; online softmax.
// ---------------------------------------------------------------------------
__global__ __launch_bounds__(64) void attn_kernel(
    const float* __restrict__ Q, const float* __restrict__ K,
    const float* __restrict__ V, float* __restrict__ Y)
{
    __shared__ float Ks[64][64];
    __shared__ float Vs[64][64];

    const int t = threadIdx.x;
    const int q0 = blockIdx.x * 64;
    const int bh = blockIdx.y;          // 0..B*H-1
    const int b = bh / HH;
    const int h = bh % HH;
    const size_t base = (size_t)b * LL * CC + (size_t)h * DD;

    const int qrow = q0 + t;
    const float* qp = Q + base + (size_t)qrow * CC;

    float qreg[DD];
#pragma unroll
    for (int d = 0; d < DD; d++) qreg[d] = qp[d] * 0.125f;  // 1/sqrt(64)

    float m = -1e30f, l = 0.0f;
    float acc[DD];
#pragma unroll
    for (int d = 0; d < DD; d++) acc[d] = 0.0f;

    for (int kt = 0; kt < LL; kt += 64) {
        __syncthreads();
        // Cooperative tile load: row i, each thread loads column t (coalesced)
        for (int i = 0; i < 64; i++) {
            size_t off = base + (size_t)(kt + i) * CC + t;
            Ks[i][t] = K[off];
            Vs[i][t] = V[off];
        }
        __syncthreads();

        for (int j = 0; j < 64; j++) {
            float s = 0.0f;
#pragma unroll
            for (int d = 0; d < DD; d++) s = fmaf(qreg[d], Ks[j][d], s);
            float mn = fmaxf(m, s);
            float corr = __expf(m - mn);   // 1.0 when max unchanged
            float p = __expf(s - mn);
            l = l * corr + p;
#pragma unroll
            for (int d = 0; d < DD; d++)
                acc[d] = fmaf(acc[d], corr, p * Vs[j][d]);
            m = mn;
        }
    }

    const float inv = 1.0f / l;
    float* yp = Y + base + (size_t)qrow * CC;
#pragma unroll
    for (int d = 0; d < DD; d++) yp[d] = acc[d] * inv;
}

// ---------------------------------------------------------------------------
// Launch
// ---------------------------------------------------------------------------
extern "C" void kernel_launch(void* const* d_in, const int* in_sizes, int n_in,
                              void* d_out, int out_size)
{
    const float* q  = (const float*)d_in[0];
    const float* k  = (const float*)d_in[1];
    const float* v  = (const float*)d_in[2];
    const float* Wq = (const float*)d_in[3];
    const float* bq = (const float*)d_in[4];
    const float* Wk = (const float*)d_in[5];
    const float* bk = (const float*)d_in[6];
    const float* Wv = (const float*)d_in[7];
    const float* bv = (const float*)d_in[8];
    const float* Wo = (const float*)d_in[9];
    const float* bo = (const float*)d_in[10];
    float* out = (float*)d_out;

    float *gq, *gk, *gv, *gy;
    cudaGetSymbolAddress((void**)&gq, g_q);
    cudaGetSymbolAddress((void**)&gk, g_k);
    cudaGetSymbolAddress((void**)&gv, g_v);
    cudaGetSymbolAddress((void**)&gy, g_y);

    dim3 ggrid(CC / 64, MTOT / 128);   // (16, 32)
    gemm_bias_kernel<<<ggrid, 256>>>(q, Wq, bq, gq);
    gemm_bias_kernel<<<ggrid, 256>>>(k, Wk, bk, gk);
    gemm_bias_kernel<<<ggrid, 256>>>(v, Wv, bv, gv);

    dim3 agrid(LL / 64, BB * HH);      // (32, 32)
    attn_kernel<<<agrid, 64>>>(gq, gk, gv, gy);

    gemm_bias_kernel<<<ggrid, 256>>>(gy, Wo, bo, out);
}

// round 7
// speedup vs baseline: 1.2885x; 1.2885x over previous
#include <cuda_runtime.h>
#include <cuda_bf16.h>
#include <cstdint>

// Problem constants (B=2, L=2048, C=1024, H=16, D=64)
#define BB 2
#define LL 2048
#define CC 1024
#define HH 16
#define DD 64
#define MTOT (BB * LL)   // 4096

// Scratch (device globals — no allocation allowed)
__device__ float g_q[MTOT * CC];
__device__ float g_k[MTOT * CC];
__device__ float g_v[MTOT * CC];
__device__ float g_y[MTOT * CC];
__device__ float g_rq[MTOT * CC];
__device__ float g_rk[MTOT * CC];
__device__ float g_rv[MTOT * CC];
__device__ float g_w[4 * CC * CC];   // tf32-rounded weights (same layout as input)

__device__ __forceinline__ float tf32_rna(float x) {
    float r;
    asm("cvt.rna.tf32.f32 %0, %1;" : "=f"(r) : "f"(x));
    return r;
}

// m16n8k8 tf32 MMA, fp32 accumulate (warp-level, works on family-level sm_103)
__device__ __forceinline__ void mma_tf32(
    float* c, uint32_t a0, uint32_t a1, uint32_t a2, uint32_t a3,
    uint32_t b0, uint32_t b1)
{
    asm volatile(
        "mma.sync.aligned.m16n8k8.row.col.f32.tf32.tf32.f32 "
        "{%0,%1,%2,%3}, {%4,%5,%6,%7}, {%8,%9}, {%0,%1,%2,%3};"
        : "+f"(c[0]), "+f"(c[1]), "+f"(c[2]), "+f"(c[3])
        : "r"(a0), "r"(a1), "r"(a2), "r"(a3), "r"(b0), "r"(b1));
}

// ---------------------------------------------------------------------------
// tf32 tensor-core GEMM + bias: Out[M,N] = A[M,K] @ W[K,N] + bias[N]
// M=4096, N=K=1024. Block tile 128x128, BK=32, 256 threads (8 warps, 4x2 grid,
// warp tile 32x64). cp.async double-buffered. A/W assumed pre-rounded to tf32.
// ---------------------------------------------------------------------------
#define A_STRIDE 36    // floats per A smem row (144B, 16B-mult, conflict-free)
#define B_STRIDE 136   // floats per B smem row (544B, 16B-mult, conflict-free)
#define A_STAGE (128 * A_STRIDE)            // floats
#define B_STAGE (32 * B_STRIDE)
#define GEMM_SMEM_FLOATS (2 * A_STAGE + 2 * B_STAGE)
#define GEMM_SMEM_BYTES (GEMM_SMEM_FLOATS * 4)   // 71680

__device__ __forceinline__ uint32_t smem_u32(const void* p) {
    uint32_t a;
    asm("{ .reg .u64 t; cvta.to.shared.u64 t, %1; cvt.u32.u64 %0, t; }"
        : "=r"(a) : "l"(p));
    return a;
}

__device__ __forceinline__ void cp16(uint32_t dst, const void* src) {
    asm volatile("cp.async.ca.shared.global [%0], [%1], 16;"
                 :: "r"(dst), "l"(src) : "memory");
}

__device__ __forceinline__ void stage_load(
    uint32_t sA, uint32_t sB,
    const float* __restrict__ A, const float* __restrict__ W,
    int m0, int n0, int k0, int tid)
{
    // A tile: 128 rows x 32 floats = 1024 16B chunks, 4 per thread
#pragma unroll
    for (int i = 0; i < 4; i++) {
        int idx = i * 256 + tid;
        int r = idx >> 3, c = idx & 7;
        cp16(sA + r * (A_STRIDE * 4) + c * 16,
             A + (size_t)(m0 + r) * CC + k0 + c * 4);
    }
    // B tile: 32 rows x 128 floats = 1024 16B chunks, 4 per thread
#pragma unroll
    for (int i = 0; i < 4; i++) {
        int idx = i * 256 + tid;
        int r = idx >> 5, c = idx & 31;
        cp16(sB + r * (B_STRIDE * 4) + c * 16,
             W + (size_t)(k0 + r) * CC + n0 + c * 4);
    }
    asm volatile("cp.async.commit_group;" ::: "memory");
}

__global__ __launch_bounds__(256, 2) void gemm_tc(
    const float* __restrict__ A, const float* __restrict__ W,
    const float* __restrict__ bias, float* __restrict__ Out)
{
    extern __shared__ float smem[];
    float* As[2] = { smem, smem + A_STAGE };
    float* Bs[2] = { smem + 2 * A_STAGE, smem + 2 * A_STAGE + B_STAGE };
    uint32_t sAu[2] = { smem_u32(As[0]), smem_u32(As[1]) };
    uint32_t sBu[2] = { smem_u32(Bs[0]), smem_u32(Bs[1]) };

    const int tid = threadIdx.x;
    const int lane = tid & 31;
    const int wid = tid >> 5;
    const int warp_m = wid & 3;        // 0..3 -> 32-row slab
    const int warp_n = wid >> 2;       // 0..1 -> 64-col slab
    const int m0 = blockIdx.y * 128;
    const int n0 = blockIdx.x * 128;

    const int lr = lane >> 2;          // 0..7
    const int lc = lane & 3;           // 0..3

    float acc[2][8][4];
#pragma unroll
    for (int mt = 0; mt < 2; mt++)
#pragma unroll
        for (int nt = 0; nt < 8; nt++)
#pragma unroll
            for (int j = 0; j < 4; j++) acc[mt][nt][j] = 0.0f;

    stage_load(sAu[0], sBu[0], A, W, m0, n0, 0, tid);

    const int NSTAGE = CC / 32;   // 32
    for (int s = 0; s < NSTAGE; s++) {
        const int buf = s & 1;
        if (s + 1 < NSTAGE) {
            stage_load(sAu[buf ^ 1], sBu[buf ^ 1], A, W, m0, n0, (s + 1) * 32, tid);
            asm volatile("cp.async.wait_group 1;" ::: "memory");
        } else {
            asm volatile("cp.async.wait_group 0;" ::: "memory");
        }
        __syncthreads();

        const uint32_t* __restrict__ Au = (const uint32_t*)As[buf];
        const uint32_t* __restrict__ Bu = (const uint32_t*)Bs[buf];
#pragma unroll
        for (int ks = 0; ks < 4; ks++) {
            const int kk = ks * 8;
            uint32_t af[2][4];
#pragma unroll
            for (int mt = 0; mt < 2; mt++) {
                int ar = warp_m * 32 + mt * 16 + lr;
                int ac = kk + lc;
                af[mt][0] = Au[ar * A_STRIDE + ac];
                af[mt][1] = Au[(ar + 8) * A_STRIDE + ac];
                af[mt][2] = Au[ar * A_STRIDE + ac + 4];
                af[mt][3] = Au[(ar + 8) * A_STRIDE + ac + 4];
            }
            uint32_t bf[8][2];
#pragma unroll
            for (int nt = 0; nt < 8; nt++) {
                int bn = warp_n * 64 + nt * 8 + lr;
                int bk = kk + lc;
                bf[nt][0] = Bu[bk * B_STRIDE + bn];
                bf[nt][1] = Bu[(bk + 4) * B_STRIDE + bn];
            }
#pragma unroll
            for (int mt = 0; mt < 2; mt++)
#pragma unroll
                for (int nt = 0; nt < 8; nt++)
                    mma_tf32(acc[mt][nt], af[mt][0], af[mt][1], af[mt][2], af[mt][3],
                             bf[nt][0], bf[nt][1]);
        }
        __syncthreads();
    }

    // Epilogue: fragment layout c0:(r, 2c) c1:(r, 2c+1) c2:(r+8, 2c) c3:(r+8, 2c+1)
#pragma unroll
    for (int mt = 0; mt < 2; mt++) {
#pragma unroll
        for (int nt = 0; nt < 8; nt++) {
            int row = m0 + warp_m * 32 + mt * 16 + lr;
            int col = n0 + warp_n * 64 + nt * 8 + 2 * lc;
            float b0 = __ldg(&bias[col]);
            float b1 = __ldg(&bias[col + 1]);
            float2 v0 = { acc[mt][nt][0] + b0, acc[mt][nt][1] + b1 };
            float2 v1 = { acc[mt][nt][2] + b0, acc[mt][nt][3] + b1 };
            *(float2*)&Out[(size_t)row * CC + col] = v0;
            *(float2*)&Out[(size_t)(row + 8) * CC + col] = v1;
        }
    }
}

// ---------------------------------------------------------------------------
// Round fp32 -> tf32 (RNA) so tensor-core ingest is exact (no truncation bias)
// ---------------------------------------------------------------------------
__global__ void round_tf32_kernel(const float* __restrict__ in, float* __restrict__ out)
{
    size_t i = ((size_t)blockIdx.x * blockDim.x + threadIdx.x) * 4;
    float4 v = *(const float4*)(in + i);
    v.x = tf32_rna(v.x); v.y = tf32_rna(v.y);
    v.z = tf32_rna(v.z); v.w = tf32_rna(v.w);
    *(float4*)(out + i) = v;
}

// ---------------------------------------------------------------------------
// Flash attention, fp32 CUDA cores. 128 threads = 128 query rows per block.
// 64-row K/V tiles, float4 LDG/LDS, rare-rescale online softmax.
// Writes Y rounded to tf32 (feeds the tf32 output projection).
// ---------------------------------------------------------------------------
__global__ __launch_bounds__(128, 3) void attn_kernel(
    const float* __restrict__ Q, const float* __restrict__ K,
    const float* __restrict__ V, float* __restrict__ Y)
{
    __shared__ float Ks[64][68];
    __shared__ float Vs[64][68];

    const int t = threadIdx.x;
    const int q0 = blockIdx.x * 128;
    const int bh = blockIdx.y;
    const int b = bh >> 4;
    const int h = bh & 15;
    const size_t base = (size_t)b * LL * CC + (size_t)h * DD;

    const float* qp = Q + base + (size_t)(q0 + t) * CC;
    float qreg[DD];
#pragma unroll
    for (int d = 0; d < DD; d += 4) {
        float4 qv = *(const float4*)(qp + d);
        qreg[d] = qv.x * 0.125f; qreg[d + 1] = qv.y * 0.125f;
        qreg[d + 2] = qv.z * 0.125f; qreg[d + 3] = qv.w * 0.125f;
    }

    float m = -1e30f, l = 0.0f;
    float acc[DD];
#pragma unroll
    for (int d = 0; d < DD; d++) acc[d] = 0.0f;

    for (int kt = 0; kt < LL; kt += 64) {
        __syncthreads();
#pragma unroll
        for (int i = 0; i < 8; i++) {
            int idx = i * 128 + t;
            int r = idx >> 4, c = idx & 15;
            size_t off = base + (size_t)(kt + r) * CC + c * 4;
            *(float4*)&Ks[r][c * 4] = *(const float4*)(K + off);
            *(float4*)&Vs[r][c * 4] = *(const float4*)(V + off);
        }
        __syncthreads();

        for (int j = 0; j < 64; j++) {
            float s = 0.0f;
#pragma unroll
            for (int d = 0; d < DD; d += 4) {
                float4 kv = *(const float4*)&Ks[j][d];
                s = fmaf(qreg[d], kv.x,
                    fmaf(qreg[d + 1], kv.y,
                    fmaf(qreg[d + 2], kv.z,
                    fmaf(qreg[d + 3], kv.w, s))));
            }
            float p;
            if (s <= m) {
                p = __expf(s - m);
            } else {
                float corr = __expf(m - s);
                m = s;
                l *= corr;
                p = 1.0f;
#pragma unroll
                for (int d = 0; d < DD; d++) acc[d] *= corr;
            }
            l += p;
#pragma unroll
            for (int d = 0; d < DD; d += 4) {
                float4 vv = *(const float4*)&Vs[j][d];
                acc[d]     = fmaf(p, vv.x, acc[d]);
                acc[d + 1] = fmaf(p, vv.y, acc[d + 1]);
                acc[d + 2] = fmaf(p, vv.z, acc[d + 2]);
                acc[d + 3] = fmaf(p, vv.w, acc[d + 3]);
            }
        }
    }

    const float inv = 1.0f / l;
    float* yp = Y + base + (size_t)(q0 + t) * CC;
#pragma unroll
    for (int d = 0; d < DD; d += 4) {
        float4 o;
        o.x = tf32_rna(acc[d] * inv);
        o.y = tf32_rna(acc[d + 1] * inv);
        o.z = tf32_rna(acc[d + 2] * inv);
        o.w = tf32_rna(acc[d + 3] * inv);
        *(float4*)(yp + d) = o;
    }
}

// ---------------------------------------------------------------------------
// Launch
// ---------------------------------------------------------------------------
extern "C" void kernel_launch(void* const* d_in, const int* in_sizes, int n_in,
                              void* d_out, int out_size)
{
    const float* q  = (const float*)d_in[0];
    const float* k  = (const float*)d_in[1];
    const float* v  = (const float*)d_in[2];
    const float* Wq = (const float*)d_in[3];
    const float* bq = (const float*)d_in[4];
    const float* Wk = (const float*)d_in[5];
    const float* bk = (const float*)d_in[6];
    const float* Wv = (const float*)d_in[7];
    const float* bv = (const float*)d_in[8];
    const float* Wo = (const float*)d_in[9];
    const float* bo = (const float*)d_in[10];
    float* out = (float*)d_out;

    float *gq, *gk, *gv, *gy, *grq, *grk, *grv, *gw;
    cudaGetSymbolAddress((void**)&gq,  g_q);
    cudaGetSymbolAddress((void**)&gk,  g_k);
    cudaGetSymbolAddress((void**)&gv,  g_v);
    cudaGetSymbolAddress((void**)&gy,  g_y);
    cudaGetSymbolAddress((void**)&grq, g_rq);
    cudaGetSymbolAddress((void**)&grk, g_rk);
    cudaGetSymbolAddress((void**)&grv, g_rv);
    cudaGetSymbolAddress((void**)&gw,  g_w);

    cudaFuncSetAttribute(gemm_tc, cudaFuncAttributeMaxDynamicSharedMemorySize,
                         GEMM_SMEM_BYTES);

    // Pre-round everything the tensor cores will read (RNA -> exact tf32 ingest)
    const int rblocks_act = (MTOT * CC) / (4 * 256);
    round_tf32_kernel<<<rblocks_act, 256>>>(q, grq);
    round_tf32_kernel<<<rblocks_act, 256>>>(k, grk);
    round_tf32_kernel<<<rblocks_act, 256>>>(v, grv);
    const int rblocks_w = (CC * CC) / (4 * 256);
    round_tf32_kernel<<<rblocks_w, 256>>>(Wq, gw + 0 * CC * CC);
    round_tf32_kernel<<<rblocks_w, 256>>>(Wk, gw + 1 * CC * CC);
    round_tf32_kernel<<<rblocks_w, 256>>>(Wv, gw + 2 * CC * CC);
    round_tf32_kernel<<<rblocks_w, 256>>>(Wo, gw + 3 * CC * CC);

    // Projections (tensor-core tf32)
    dim3 ggrid(CC / 128, MTOT / 128);   // (8, 32)
    gemm_tc<<<ggrid, 256, GEMM_SMEM_BYTES>>>(grq, gw + 0 * CC * CC, bq, gq);
    gemm_tc<<<ggrid, 256, GEMM_SMEM_BYTES>>>(grk, gw + 1 * CC * CC, bk, gk);
    gemm_tc<<<ggrid, 256, GEMM_SMEM_BYTES>>>(grv, gw + 2 * CC * CC, bv, gv);

    // Attention (fp32 flash)
    dim3 agrid(LL / 128, BB * HH);      // (16, 32)
    attn_kernel<<<agrid, 128>>>(gq, gk, gv, gy);

    // Output projection (tensor-core tf32); y already tf32-rounded in attn epilogue
    gemm_tc<<<ggrid, 256, GEMM_SMEM_BYTES>>>(gy, gw + 3 * CC * CC, bo, out);
}

// round 8
// speedup vs baseline: 5.1400x; 3.9893x over previous
#include <cuda_runtime.h>
#include <cuda_bf16.h>
#include <cstdint>

// Problem constants (B=2, L=2048, C=1024, H=16, D=64)
#define BB 2
#define LL 2048
#define CC 1024
#define HH 16
#define DD 64
#define MTOT (BB * LL)   // 4096

// Scratch (device globals — no allocation allowed)
__device__ float g_q[MTOT * CC];
__device__ float g_k[MTOT * CC];
__device__ float g_v[MTOT * CC];
__device__ float g_y[MTOT * CC];
__device__ float g_rq[MTOT * CC];
__device__ float g_rk[MTOT * CC];
__device__ float g_rv[MTOT * CC];
__device__ float g_w[4 * CC * CC];   // tf32-rounded weights (same layout as input)

__device__ __forceinline__ float tf32_rna(float x) {
    float r;
    asm("cvt.rna.tf32.f32 %0, %1;" : "=f"(r) : "f"(x));
    return r;
}

// m16n8k8 tf32 MMA, fp32 accumulate
__device__ __forceinline__ void mma_tf32(
    float* c, uint32_t a0, uint32_t a1, uint32_t a2, uint32_t a3,
    uint32_t b0, uint32_t b1)
{
    asm volatile(
        "mma.sync.aligned.m16n8k8.row.col.f32.tf32.tf32.f32 "
        "{%0,%1,%2,%3}, {%4,%5,%6,%7}, {%8,%9}, {%0,%1,%2,%3};"
        : "+f"(c[0]), "+f"(c[1]), "+f"(c[2]), "+f"(c[3])
        : "r"(a0), "r"(a1), "r"(a2), "r"(a3), "r"(b0), "r"(b1));
}

// m16n8k16 bf16 MMA, fp32 accumulate
__device__ __forceinline__ void mma_bf16(
    float* c, uint32_t a0, uint32_t a1, uint32_t a2, uint32_t a3,
    uint32_t b0, uint32_t b1)
{
    asm volatile(
        "mma.sync.aligned.m16n8k16.row.col.f32.bf16.bf16.f32 "
        "{%0,%1,%2,%3}, {%4,%5,%6,%7}, {%8,%9}, {%0,%1,%2,%3};"
        : "+f"(c[0]), "+f"(c[1]), "+f"(c[2]), "+f"(c[3])
        : "r"(a0), "r"(a1), "r"(a2), "r"(a3), "r"(b0), "r"(b1));
}

__device__ __forceinline__ uint32_t smem_u32(const void* p) {
    uint32_t a;
    asm("{ .reg .u64 t; cvta.to.shared.u64 t, %1; cvt.u32.u64 %0, t; }"
        : "=r"(a) : "l"(p));
    return a;
}

__device__ __forceinline__ void cp16(uint32_t dst, const void* src) {
    asm volatile("cp.async.ca.shared.global [%0], [%1], 16;"
                 :: "r"(dst), "l"(src) : "memory");
}

__device__ __forceinline__ uint32_t pack_bf16x2(float lo, float hi) {
    __nv_bfloat162 h = __float22bfloat162_rn(make_float2(lo, hi));
    return *reinterpret_cast<uint32_t*>(&h);
}

// ---------------------------------------------------------------------------
// tf32 tensor-core GEMM + bias (unchanged from passing round 7)
// ---------------------------------------------------------------------------
#define A_STRIDE 36
#define B_STRIDE 136
#define A_STAGE (128 * A_STRIDE)
#define B_STAGE (32 * B_STRIDE)
#define GEMM_SMEM_FLOATS (2 * A_STAGE + 2 * B_STAGE)
#define GEMM_SMEM_BYTES (GEMM_SMEM_FLOATS * 4)   // 71680

__device__ __forceinline__ void stage_load(
    uint32_t sA, uint32_t sB,
    const float* __restrict__ A, const float* __restrict__ W,
    int m0, int n0, int k0, int tid)
{
#pragma unroll
    for (int i = 0; i < 4; i++) {
        int idx = i * 256 + tid;
        int r = idx >> 3, c = idx & 7;
        cp16(sA + r * (A_STRIDE * 4) + c * 16,
             A + (size_t)(m0 + r) * CC + k0 + c * 4);
    }
#pragma unroll
    for (int i = 0; i < 4; i++) {
        int idx = i * 256 + tid;
        int r = idx >> 5, c = idx & 31;
        cp16(sB + r * (B_STRIDE * 4) + c * 16,
             W + (size_t)(k0 + r) * CC + n0 + c * 4);
    }
    asm volatile("cp.async.commit_group;" ::: "memory");
}

__global__ __launch_bounds__(256, 2) void gemm_tc(
    const float* __restrict__ A, const float* __restrict__ W,
    const float* __restrict__ bias, float* __restrict__ Out)
{
    extern __shared__ float smem[];
    float* As[2] = { smem, smem + A_STAGE };
    float* Bs[2] = { smem + 2 * A_STAGE, smem + 2 * A_STAGE + B_STAGE };
    uint32_t sAu[2] = { smem_u32(As[0]), smem_u32(As[1]) };
    uint32_t sBu[2] = { smem_u32(Bs[0]), smem_u32(Bs[1]) };

    const int tid = threadIdx.x;
    const int lane = tid & 31;
    const int wid = tid >> 5;
    const int warp_m = wid & 3;
    const int warp_n = wid >> 2;
    const int m0 = blockIdx.y * 128;
    const int n0 = blockIdx.x * 128;
    const int lr = lane >> 2;
    const int lc = lane & 3;

    float acc[2][8][4];
#pragma unroll
    for (int mt = 0; mt < 2; mt++)
#pragma unroll
        for (int nt = 0; nt < 8; nt++)
#pragma unroll
            for (int j = 0; j < 4; j++) acc[mt][nt][j] = 0.0f;

    stage_load(sAu[0], sBu[0], A, W, m0, n0, 0, tid);

    const int NSTAGE = CC / 32;
    for (int s = 0; s < NSTAGE; s++) {
        const int buf = s & 1;
        if (s + 1 < NSTAGE) {
            stage_load(sAu[buf ^ 1], sBu[buf ^ 1], A, W, m0, n0, (s + 1) * 32, tid);
            asm volatile("cp.async.wait_group 1;" ::: "memory");
        } else {
            asm volatile("cp.async.wait_group 0;" ::: "memory");
        }
        __syncthreads();

        const uint32_t* __restrict__ Au = (const uint32_t*)As[buf];
        const uint32_t* __restrict__ Bu = (const uint32_t*)Bs[buf];
#pragma unroll
        for (int ks = 0; ks < 4; ks++) {
            const int kk = ks * 8;
            uint32_t af[2][4];
#pragma unroll
            for (int mt = 0; mt < 2; mt++) {
                int ar = warp_m * 32 + mt * 16 + lr;
                int ac = kk + lc;
                af[mt][0] = Au[ar * A_STRIDE + ac];
                af[mt][1] = Au[(ar + 8) * A_STRIDE + ac];
                af[mt][2] = Au[ar * A_STRIDE + ac + 4];
                af[mt][3] = Au[(ar + 8) * A_STRIDE + ac + 4];
            }
            uint32_t bf[8][2];
#pragma unroll
            for (int nt = 0; nt < 8; nt++) {
                int bn = warp_n * 64 + nt * 8 + lr;
                int bk = kk + lc;
                bf[nt][0] = Bu[bk * B_STRIDE + bn];
                bf[nt][1] = Bu[(bk + 4) * B_STRIDE + bn];
            }
#pragma unroll
            for (int mt = 0; mt < 2; mt++)
#pragma unroll
                for (int nt = 0; nt < 8; nt++)
                    mma_tf32(acc[mt][nt], af[mt][0], af[mt][1], af[mt][2], af[mt][3],
                             bf[nt][0], bf[nt][1]);
        }
        __syncthreads();
    }

#pragma unroll
    for (int mt = 0; mt < 2; mt++) {
#pragma unroll
        for (int nt = 0; nt < 8; nt++) {
            int row = m0 + warp_m * 32 + mt * 16 + lr;
            int col = n0 + warp_n * 64 + nt * 8 + 2 * lc;
            float b0 = __ldg(&bias[col]);
            float b1 = __ldg(&bias[col + 1]);
            float2 v0 = { acc[mt][nt][0] + b0, acc[mt][nt][1] + b1 };
            float2 v1 = { acc[mt][nt][2] + b0, acc[mt][nt][3] + b1 };
            *(float2*)&Out[(size_t)row * CC + col] = v0;
            *(float2*)&Out[(size_t)(row + 8) * CC + col] = v1;
        }
    }
}

// ---------------------------------------------------------------------------
// Round fp32 -> tf32 (RNA)
// ---------------------------------------------------------------------------
__global__ void round_tf32_kernel(const float* __restrict__ in, float* __restrict__ out)
{
    size_t i = ((size_t)blockIdx.x * blockDim.x + threadIdx.x) * 4;
    float4 v = *(const float4*)(in + i);
    v.x = tf32_rna(v.x); v.y = tf32_rna(v.y);
    v.z = tf32_rna(v.z); v.w = tf32_rna(v.w);
    *(float4*)(out + i) = v;
}

// ---------------------------------------------------------------------------
// Tensor-core flash attention.
// CTA = 128 threads (4 warps), q-tile = 64 rows (warp w owns rows w*16..+15).
// k-tiles of 64 keys, K/V cp.async double-buffered.
// QK^T: tf32 m16n8k8 (K smem [64][68] f32). Softmax on fragments.
// P.V:  bf16 m16n8k16, V transposed to bf16 smem [d=64][key+pad=72].
// ---------------------------------------------------------------------------
#define KS_STRIDE 68     // floats per K/V-stage smem row
#define VT_STRIDE 72     // bf16 per Vt smem row
#define KV_TILE_B (64 * KS_STRIDE * 4)   // 17408 bytes
// smem layout (bytes): Ks0 | Ks1 | Vs0 | Vs1 | Vt
#define ATT_VT_OFF (4 * KV_TILE_B)
#define ATT_SMEM_BYTES (4 * KV_TILE_B + 64 * VT_STRIDE * 2)   // 78848

__device__ __forceinline__ void attn_stage_kv(
    uint32_t ksu, uint32_t vsu,
    const float* __restrict__ K, const float* __restrict__ V,
    size_t base, int kt, int tid)
{
#pragma unroll
    for (int i = 0; i < 8; i++) {
        int idx = i * 128 + tid;
        int r = idx >> 4, c = idx & 15;
        cp16(ksu + r * (KS_STRIDE * 4) + c * 16,
             K + base + (size_t)(kt * 64 + r) * CC + c * 4);
    }
#pragma unroll
    for (int i = 0; i < 8; i++) {
        int idx = i * 128 + tid;
        int r = idx >> 4, c = idx & 15;
        cp16(vsu + r * (KS_STRIDE * 4) + c * 16,
             V + base + (size_t)(kt * 64 + r) * CC + c * 4);
    }
    asm volatile("cp.async.commit_group;" ::: "memory");
}

__global__ __launch_bounds__(128, 2) void attn_tc(
    const float* __restrict__ Q, const float* __restrict__ K,
    const float* __restrict__ V, float* __restrict__ Y)
{
    extern __shared__ float smem[];
    float* Ks[2] = { smem, smem + KV_TILE_B / 4 };
    float* Vs[2] = { smem + 2 * (KV_TILE_B / 4), smem + 3 * (KV_TILE_B / 4) };
    __nv_bfloat16* Vt = (__nv_bfloat16*)((char*)smem + ATT_VT_OFF);
    uint32_t ksu[2] = { smem_u32(Ks[0]), smem_u32(Ks[1]) };
    uint32_t vsu[2] = { smem_u32(Vs[0]), smem_u32(Vs[1]) };

    const int tid = threadIdx.x;
    const int lane = tid & 31;
    const int w = tid >> 5;
    const int lr = lane >> 2;
    const int lc = lane & 3;
    const int q0 = blockIdx.x * 64;
    const int bh = blockIdx.y;
    const int b = bh >> 4;
    const int h = bh & 15;
    const size_t base = (size_t)b * LL * CC + (size_t)h * DD;

    // --- Stage Q (scaled by 1/8) into Vs[0], build register A-fragments ---
    {
        float* Qs = Vs[0];
#pragma unroll
        for (int i = 0; i < 8; i++) {
            int idx = i * 128 + tid;
            int r = idx >> 4, c4 = (idx & 15) * 4;
            float4 qv = *(const float4*)(Q + base + (size_t)(q0 + r) * CC + c4);
            qv.x *= 0.125f; qv.y *= 0.125f; qv.z *= 0.125f; qv.w *= 0.125f;
            *(float4*)&Qs[r * KS_STRIDE + c4] = qv;
        }
    }
    __syncthreads();
    uint32_t qa[8][4];
    {
        const uint32_t* Qs = (const uint32_t*)Vs[0];
        const int row = w * 16 + lr;
#pragma unroll
        for (int ks = 0; ks < 8; ks++) {
            int col = ks * 8 + lc;
            qa[ks][0] = Qs[row * KS_STRIDE + col];
            qa[ks][1] = Qs[(row + 8) * KS_STRIDE + col];
            qa[ks][2] = Qs[row * KS_STRIDE + col + 4];
            qa[ks][3] = Qs[(row + 8) * KS_STRIDE + col + 4];
        }
    }
    __syncthreads();   // done with Vs[0] as Q staging

    // --- Prologue prefetch tile 0 ---
    attn_stage_kv(ksu[0], vsu[0], K, V, base, 0, tid);

    float oacc[8][4];
#pragma unroll
    for (int dt = 0; dt < 8; dt++)
#pragma unroll
        for (int j = 0; j < 4; j++) oacc[dt][j] = 0.0f;
    float m0 = -1e30f, m1 = -1e30f, l0 = 0.0f, l1 = 0.0f;

    const int NT = LL / 64;   // 32
    for (int kt = 0; kt < NT; kt++) {
        const int buf = kt & 1;
        if (kt + 1 < NT) {
            attn_stage_kv(ksu[buf ^ 1], vsu[buf ^ 1], K, V, base, kt + 1, tid);
            asm volatile("cp.async.wait_group 1;" ::: "memory");
        } else {
            asm volatile("cp.async.wait_group 0;" ::: "memory");
        }
        __syncthreads();

        // Convert V stage -> Vt bf16 transposed [d][key]
        {
            const float* Vsb = Vs[buf];
            const int d = tid & 63;
            const int kp0 = (tid >> 6) * 16;
#pragma unroll
            for (int j = 0; j < 16; j++) {
                int key = (kp0 + j) * 2;
                float f0 = Vsb[key * KS_STRIDE + d];
                float f1 = Vsb[(key + 1) * KS_STRIDE + d];
                *(uint32_t*)&Vt[d * VT_STRIDE + key] = pack_bf16x2(f0, f1);
            }
        }
        __syncthreads();

        // --- S = Q K^T (tf32) ---
        float sacc[8][4];
#pragma unroll
        for (int nt = 0; nt < 8; nt++)
#pragma unroll
            for (int j = 0; j < 4; j++) sacc[nt][j] = 0.0f;

        const uint32_t* Ku = (const uint32_t*)Ks[buf];
#pragma unroll
        for (int ks = 0; ks < 8; ks++) {
            uint32_t kb[8][2];
#pragma unroll
            for (int nt = 0; nt < 8; nt++) {
                int krow = nt * 8 + lr;
                int kcol = ks * 8 + lc;
                kb[nt][0] = Ku[krow * KS_STRIDE + kcol];
                kb[nt][1] = Ku[krow * KS_STRIDE + kcol + 4];
            }
#pragma unroll
            for (int nt = 0; nt < 8; nt++)
                mma_tf32(sacc[nt], qa[ks][0], qa[ks][1], qa[ks][2], qa[ks][3],
                         kb[nt][0], kb[nt][1]);
        }

        // --- Online softmax on fragments ---
        float tmax0 = -1e30f, tmax1 = -1e30f;
#pragma unroll
        for (int nt = 0; nt < 8; nt++) {
            tmax0 = fmaxf(tmax0, fmaxf(sacc[nt][0], sacc[nt][1]));
            tmax1 = fmaxf(tmax1, fmaxf(sacc[nt][2], sacc[nt][3]));
        }
        tmax0 = fmaxf(tmax0, __shfl_xor_sync(0xffffffffu, tmax0, 1));
        tmax0 = fmaxf(tmax0, __shfl_xor_sync(0xffffffffu, tmax0, 2));
        tmax1 = fmaxf(tmax1, __shfl_xor_sync(0xffffffffu, tmax1, 1));
        tmax1 = fmaxf(tmax1, __shfl_xor_sync(0xffffffffu, tmax1, 2));

        float mn0 = fmaxf(m0, tmax0);
        float mn1 = fmaxf(m1, tmax1);
        float corr0 = __expf(m0 - mn0);
        float corr1 = __expf(m1 - mn1);
        m0 = mn0; m1 = mn1;

        float sum0 = 0.0f, sum1 = 0.0f;
#pragma unroll
        for (int nt = 0; nt < 8; nt++) {
            sacc[nt][0] = __expf(sacc[nt][0] - mn0);
            sacc[nt][1] = __expf(sacc[nt][1] - mn0);
            sacc[nt][2] = __expf(sacc[nt][2] - mn1);
            sacc[nt][3] = __expf(sacc[nt][3] - mn1);
            sum0 += sacc[nt][0] + sacc[nt][1];
            sum1 += sacc[nt][2] + sacc[nt][3];
        }
        sum0 += __shfl_xor_sync(0xffffffffu, sum0, 1);
        sum0 += __shfl_xor_sync(0xffffffffu, sum0, 2);
        sum1 += __shfl_xor_sync(0xffffffffu, sum1, 1);
        sum1 += __shfl_xor_sync(0xffffffffu, sum1, 2);
        l0 = l0 * corr0 + sum0;
        l1 = l1 * corr1 + sum1;

        // --- P -> bf16 A-fragments (acc layout == A layout, no shuffles) ---
        uint32_t pa[4][4];
#pragma unroll
        for (int s = 0; s < 4; s++) {
            pa[s][0] = pack_bf16x2(sacc[2 * s][0], sacc[2 * s][1]);
            pa[s][1] = pack_bf16x2(sacc[2 * s][2], sacc[2 * s][3]);
            pa[s][2] = pack_bf16x2(sacc[2 * s + 1][0], sacc[2 * s + 1][1]);
            pa[s][3] = pack_bf16x2(sacc[2 * s + 1][2], sacc[2 * s + 1][3]);
        }

        // --- Rescale O, then O += P V (bf16) ---
#pragma unroll
        for (int dt = 0; dt < 8; dt++) {
            oacc[dt][0] *= corr0; oacc[dt][1] *= corr0;
            oacc[dt][2] *= corr1; oacc[dt][3] *= corr1;
        }
#pragma unroll
        for (int s = 0; s < 4; s++) {
#pragma unroll
            for (int dt = 0; dt < 8; dt++) {
                int vrow = dt * 8 + lr;
                uint32_t b0 = *(const uint32_t*)&Vt[vrow * VT_STRIDE + s * 16 + 2 * lc];
                uint32_t b1 = *(const uint32_t*)&Vt[vrow * VT_STRIDE + s * 16 + 2 * lc + 8];
                mma_bf16(oacc[dt], pa[s][0], pa[s][1], pa[s][2], pa[s][3], b0, b1);
            }
        }
    }

    // --- Epilogue: normalize, tf32-round (feeds final GEMM), store ---
    const float inv0 = 1.0f / l0;
    const float inv1 = 1.0f / l1;
    const int r0 = q0 + w * 16 + lr;
    const int r1 = r0 + 8;
#pragma unroll
    for (int dt = 0; dt < 8; dt++) {
        int col = dt * 8 + 2 * lc;
        float2 v0 = { tf32_rna(oacc[dt][0] * inv0), tf32_rna(oacc[dt][1] * inv0) };
        float2 v1 = { tf32_rna(oacc[dt][2] * inv1), tf32_rna(oacc[dt][3] * inv1) };
        *(float2*)&Y[base + (size_t)r0 * CC + col] = v0;
        *(float2*)&Y[base + (size_t)r1 * CC + col] = v1;
    }
}

// ---------------------------------------------------------------------------
// Launch
// ---------------------------------------------------------------------------
extern "C" void kernel_launch(void* const* d_in, const int* in_sizes, int n_in,
                              void* d_out, int out_size)
{
    const float* q  = (const float*)d_in[0];
    const float* k  = (const float*)d_in[1];
    const float* v  = (const float*)d_in[2];
    const float* Wq = (const float*)d_in[3];
    const float* bq = (const float*)d_in[4];
    const float* Wk = (const float*)d_in[5];
    const float* bk = (const float*)d_in[6];
    const float* Wv = (const float*)d_in[7];
    const float* bv = (const float*)d_in[8];
    const float* Wo = (const float*)d_in[9];
    const float* bo = (const float*)d_in[10];
    float* out = (float*)d_out;

    float *gq, *gk, *gv, *gy, *grq, *grk, *grv, *gw;
    cudaGetSymbolAddress((void**)&gq,  g_q);
    cudaGetSymbolAddress((void**)&gk,  g_k);
    cudaGetSymbolAddress((void**)&gv,  g_v);
    cudaGetSymbolAddress((void**)&gy,  g_y);
    cudaGetSymbolAddress((void**)&grq, g_rq);
    cudaGetSymbolAddress((void**)&grk, g_rk);
    cudaGetSymbolAddress((void**)&grv, g_rv);
    cudaGetSymbolAddress((void**)&gw,  g_w);

    cudaFuncSetAttribute(gemm_tc, cudaFuncAttributeMaxDynamicSharedMemorySize,
                         GEMM_SMEM_BYTES);
    cudaFuncSetAttribute(attn_tc, cudaFuncAttributeMaxDynamicSharedMemorySize,
                         ATT_SMEM_BYTES);

    // Pre-round tensor-core inputs (RNA -> exact tf32 ingest)
    const int rblocks_act = (MTOT * CC) / (4 * 256);
    round_tf32_kernel<<<rblocks_act, 256>>>(q, grq);
    round_tf32_kernel<<<rblocks_act, 256>>>(k, grk);
    round_tf32_kernel<<<rblocks_act, 256>>>(v, grv);
    const int rblocks_w = (CC * CC) / (4 * 256);
    round_tf32_kernel<<<rblocks_w, 256>>>(Wq, gw + 0 * CC * CC);
    round_tf32_kernel<<<rblocks_w, 256>>>(Wk, gw + 1 * CC * CC);
    round_tf32_kernel<<<rblocks_w, 256>>>(Wv, gw + 2 * CC * CC);
    round_tf32_kernel<<<rblocks_w, 256>>>(Wo, gw + 3 * CC * CC);

    // Projections (tensor-core tf32)
    dim3 ggrid(CC / 128, MTOT / 128);   // (8, 32)
    gemm_tc<<<ggrid, 256, GEMM_SMEM_BYTES>>>(grq, gw + 0 * CC * CC, bq, gq);
    gemm_tc<<<ggrid, 256, GEMM_SMEM_BYTES>>>(grk, gw + 1 * CC * CC, bk, gk);
    gemm_tc<<<ggrid, 256, GEMM_SMEM_BYTES>>>(grv, gw + 2 * CC * CC, bv, gv);

    // Attention (tensor-core flash)
    dim3 agrid(LL / 64, BB * HH);       // (32, 32)
    attn_tc<<<agrid, 128, ATT_SMEM_BYTES>>>(gq, gk, gv, gy);

    // Output projection (tensor-core tf32); y tf32-rounded in attn epilogue
    gemm_tc<<<ggrid, 256, GEMM_SMEM_BYTES>>>(gy, gw + 3 * CC * CC, bo, out);
}